// round 2
// baseline (speedup 1.0000x reference)
#include <cuda_runtime.h>
#include <math.h>

#define KNUM 1024
#define DNUM 64
#define NNUM 32768          // 32 * 32 * 32 tokens
#define TB   128            // threads per block, assign kernel
#define CH   128            // codebook rows cached in smem per chunk
#define NBLK (NNUM / TB)    // 256 blocks
#define HWB  6              // OT band half-width (f32-exact; farther terms vanish)
#define DUAL_STEPS 10

// ---- scratch (no device allocation allowed) ----
__device__ float g_cc[KNUM];        // ||codebook_k||^2 (accurate f32)
__device__ int   g_hist[KNUM];      // hard assignment counts
__device__ float g_msep[NBLK];      // per-block MSE partial sums

// ============================================================
// Kernel 0: zero hist, compute codebook squared norms
// ============================================================
__global__ void prep_kernel(const float* __restrict__ cb) {
    int k = blockIdx.x * blockDim.x + threadIdx.x;
    if (k < KNUM) {
        g_hist[k] = 0;
        const float* r = cb + (size_t)k * DNUM;
        float s = 0.f;
        #pragma unroll
        for (int d = 0; d < DNUM; ++d) s = fmaf(r[d], r[d], s);
        g_cc[k] = s;   // cc error ~1e-12, far below the d-grid (7.6e-6): irrelevant
    }
}

// ============================================================
// Kernel 1: per-token argmin emulating reference f32 numerics:
//   d_k = fl( fl(xxr + cc_k) - 2*t_k )
//   xxr = XLA-GPU-style warp-tree f32 reduce of squares
//   t_k = accurate f32 dot (error ~1e-9, below grid sensitivity)
// ============================================================
__global__ __launch_bounds__(TB) void assign_kernel(const float* __restrict__ x,
                                                    const float* __restrict__ cb,
                                                    float* __restrict__ out) {
    __shared__ float scb[CH * DNUM];   // 32 KB codebook chunk
    __shared__ float scc[CH];
    __shared__ float sred[TB];

    const int n  = blockIdx.x * TB + threadIdx.x;   // token index (b*1024 + h*32 + w)
    const int b  = n >> 10;
    const int hw = n & 1023;
    // inputs layout [B, C=64, H, W]: element (b, c, hw) at b*65536 + c*1024 + hw
    const float* xp = x + (size_t)b * (DNUM * 1024) + hw;

    float4 xr[16];
    #pragma unroll
    for (int c4 = 0; c4 < 16; ++c4) {
        xr[c4].x = xp[(size_t)(c4 * 4 + 0) * 1024];
        xr[c4].y = xp[(size_t)(c4 * 4 + 1) * 1024];
        xr[c4].z = xp[(size_t)(c4 * 4 + 2) * 1024];
        xr[c4].w = xp[(size_t)(c4 * 4 + 3) * 1024];
    }
    const float* xf = (const float*)xr;

    // ---- emulate reference f32 row-sum of squares (XLA GPU warp row-reduce):
    //   lane partial p[l] = fl( fl(x_l^2) + fl(x_{l+32}^2) )
    //   then shfl-down tree: offsets 16, 8, 4, 2, 1
    // All via __fmul_rn/__fadd_rn so no FMA contraction changes rounding.
    float p[32];
    #pragma unroll
    for (int l = 0; l < 32; ++l)
        p[l] = __fadd_rn(__fmul_rn(xf[l], xf[l]),
                         __fmul_rn(xf[l + 32], xf[l + 32]));
    #pragma unroll
    for (int off = 16; off > 0; off >>= 1)
        #pragma unroll
        for (int l = 0; l < 16; ++l)
            if (l < off) p[l] = __fadd_rn(p[l], p[l + off]);
    const float xxr = p[0];

    float best = INFINITY;
    int   bidx = 0;

    for (int k0 = 0; k0 < KNUM; k0 += CH) {
        __syncthreads();
        const float4* s4 = (const float4*)(cb + (size_t)k0 * DNUM);
        float4*       d4 = (float4*)scb;
        #pragma unroll 4
        for (int i = threadIdx.x; i < CH * DNUM / 4; i += TB) d4[i] = s4[i];
        scc[threadIdx.x] = g_cc[k0 + threadIdx.x];   // TB == CH
        __syncthreads();

        for (int kk = 0; kk < CH; ++kk) {
            const float4* cp = (const float4*)(scb + kk * DNUM);
            float a0 = 0.f, a1 = 0.f, a2 = 0.f, a3 = 0.f;
            #pragma unroll
            for (int c4 = 0; c4 < 16; ++c4) {
                float4 cv = cp[c4];
                a0 = fmaf(xr[c4].x, cv.x, a0);
                a1 = fmaf(xr[c4].y, cv.y, a1);
                a2 = fmaf(xr[c4].z, cv.z, a2);
                a3 = fmaf(xr[c4].w, cv.w, a3);
            }
            float t  = __fadd_rn(__fadd_rn(a0, a1), __fadd_rn(a2, a3)); // accurate dot
            // reference assembly, rounded exactly as f32 does it:
            float u  = __fadd_rn(xxr, scc[kk]);          // fl(xx + cc_k)
            float dk = __fadd_rn(u, __fmul_rn(-2.f, t)); // fl(u - 2 t_k)
            if (dk < best) { best = dk; bidx = k0 + kk; } // strict < => first-index min
        }
    }

    atomicAdd(&g_hist[bidx], 1);

    // quantized output (= chosen codeword) in [B,C,H,W] layout + MSE
    const float* cw = cb + (size_t)bidx * DNUM;
    float*       op = out + (size_t)b * (DNUM * 1024) + hw;
    float mse = 0.f;
    #pragma unroll
    for (int c = 0; c < DNUM; ++c) {
        float cv = cw[c];
        op[(size_t)c * 1024] = cv;
        float dd = cv - xf[c];
        mse = fmaf(dd, dd, mse);
    }

    sred[threadIdx.x] = mse;
    __syncthreads();
    for (int s = TB / 2; s > 0; s >>= 1) {
        if (threadIdx.x < s) sred[threadIdx.x] += sred[threadIdx.x + s];
        __syncthreads();
    }
    if (threadIdx.x == 0) g_msep[blockIdx.x] = sred[0];
}

// ============================================================
// Kernel 2: perplexity, entropic-OT dual ascent (banded), loss
// ============================================================
__device__ __forceinline__ float bred(float v, float* red, int t) {
    __syncthreads();
    red[t] = v;
    __syncthreads();
    for (int s = 512; s > 0; s >>= 1) {
        if (t < s) red[t] += red[t + s];
        __syncthreads();
    }
    float r = red[0];
    __syncthreads();
    return r;
}

__global__ __launch_bounds__(1024) void finalize_kernel(float* __restrict__ out) {
    __shared__ float s_src[KNUM], s_tgt[KNUM], s_phi[KNUM], s_lse[KNUM], s_ltg[KNUM];
    __shared__ float red[1024];
    const int t = threadIdx.x;

    const float hist = (float)g_hist[t] * (1.0f / 32768.0f);

    // perplexity = exp(-sum p*log(p+1e-10))
    float ent  = hist * logf(hist + 1e-10f);
    float esum = bred(ent, red, t);
    float perp = expf(-esum);

    // src = norm_prob(norm_prob(hard_hist))
    float sr  = fmaxf(hist, 1e-12f);
    float ss1 = bred(sr, red, t);
    sr = sr / ss1;
    sr = fmaxf(sr, 1e-12f);
    float ss2 = bred(sr, red, t);
    sr = sr / ss2;
    s_src[t] = sr;

    // gaussian target, normalized twice
    float z  = ((float)t - 511.5f) / (1024.0f / 6.0f);
    float tg = expf(-0.5f * z * z);
    float ts1 = bred(tg, red, t);
    tg = tg / fmaxf(ts1, 1e-12f);
    tg = fmaxf(tg, 1e-12f);
    float ts2 = bred(tg, red, t);
    tg = tg / ts2;
    s_tgt[t] = tg;
    s_ltg[t] = logf(fmaxf(tg, 1e-12f));
    s_phi[t] = 0.f;
    __syncthreads();

    const int lo = (t - HWB < 0) ? 0 : t - HWB;
    const int hi = (t + HWB > KNUM - 1) ? KNUM - 1 : t + HWB;

    for (int step = 0; step <= DUAL_STEPS; ++step) {
        float m = -INFINITY;
        for (int j = lo; j <= hi; ++j) {
            float a = s_ltg[j] + (s_phi[j] - fabsf((float)(t - j))) / 0.05f;
            m = fmaxf(m, a);
        }
        float s = 0.f;
        for (int j = lo; j <= hi; ++j) {
            float a = s_ltg[j] + (s_phi[j] - fabsf((float)(t - j))) / 0.05f;
            s += expf(a - m);
        }
        s_lse[t] = m + logf(s);
        __syncthreads();
        if (step == DUAL_STEPS) break;

        float cs = 0.f;
        const float ltg_t = s_ltg[t];
        const float phi_t = s_phi[t];
        for (int i = lo; i <= hi; ++i) {
            float a = ltg_t + (phi_t - fabsf((float)(i - t))) / 0.05f;
            cs = fmaf(s_src[i], expf(a - s_lse[i]), cs);
        }
        __syncthreads();
        s_phi[t] = phi_t + 0.5f * (s_tgt[t] - cs);
        __syncthreads();
    }

    float obj = sr * (-0.05f * s_lse[t]) + s_tgt[t] * s_phi[t];
    float ot  = bred(obj, red, t);

    float mp   = (t < NBLK) ? g_msep[t] : 0.f;
    float msum = bred(mp, red, t);
    float mse  = msum * (1.0f / 2097152.0f);

    if (t == 0) {
        float loss = mse + 0.25f * mse + 1.0f * ot;   // codebook + CC*commit + OT
        out[2097152] = loss;
        out[2097153] = perp;
    }
}

// ============================================================
extern "C" void kernel_launch(void* const* d_in, const int* in_sizes, int n_in,
                              void* d_out, int out_size) {
    const float* x  = (const float*)d_in[0];   // inputs  [32,64,32,32]
    const float* cb = (const float*)d_in[1];   // codebook [1024,64]
    float* out = (float*)d_out;
    (void)in_sizes; (void)n_in; (void)out_size;

    prep_kernel<<<4, 256>>>(cb);
    assign_kernel<<<NBLK, TB>>>(x, cb, out);
    finalize_kernel<<<1, 1024>>>(out);
}